// round 5
// baseline (speedup 1.0000x reference)
#include <cuda_runtime.h>
#include <cstdint>

#define VOCAB   128000
#define VOCAB4  32000
#define ROWS    256
#define CPR     8                 // chunks per row (K1)
#define CF4     (VOCAB4 / CPR)    // 4000 float4 per chunk
#define K1_NT   512
#define K1_IT   ((CF4 + K1_NT - 1) / K1_NT)   // 8 (last predicated)
#define CAP     8192
#define SUBCAP  512
#define NEGV    (-1000000000.0f)
#define FULLMASK 0xffffffffu

// __device__ global scratch (allocation-free rule compliant)
__device__ unsigned long long g_cand[(size_t)ROWS * CAP];   // 16 MB (val<<32 | idx)
__device__ int   g_cnt[ROWS * 32];                          // 128B-strided counters
__device__ float g_t0[ROWS];
__device__ float g_M[ROWS];

// ======================= K0: sample -> t0, M; zero counters =======================
__global__ __launch_bounds__(1024, 2)
void k0_sample(const float* __restrict__ in) {
    __shared__ float warp2nd[32];
    __shared__ float warpmax[32];
    const int tid  = threadIdx.x;
    const int lane = tid & 31;
    const int wid  = tid >> 5;
    const float* __restrict__ x = in + (size_t)blockIdx.x * VOCAB;

    const float4* __restrict__ xs = (const float4*)(x + wid * 4000);
    float4 sa = xs[lane * 2];
    float4 sb = xs[lane * 2 + 1];
    float sv[8] = {sa.x, sa.y, sa.z, sa.w, sb.x, sb.y, sb.z, sb.w};

    float lm = sv[0];
#pragma unroll
    for (int k = 1; k < 8; k++) lm = fmaxf(lm, sv[k]);
    float wm = lm;
#pragma unroll
    for (int off = 16; off > 0; off >>= 1)
        wm = fmaxf(wm, __shfl_xor_sync(FULLMASK, wm, off));
    unsigned bal = __ballot_sync(FULLMASK, lm == wm);
    if (lane == (__ffs(bal) - 1)) {
        bool done = false;
#pragma unroll
        for (int k = 0; k < 8; k++)
            if (!done && sv[k] == wm) { sv[k] = -3.4e38f; done = true; }
    }
    float lm2 = sv[0];
#pragma unroll
    for (int k = 1; k < 8; k++) lm2 = fmaxf(lm2, sv[k]);
    float wm2 = lm2;
#pragma unroll
    for (int off = 16; off > 0; off >>= 1)
        wm2 = fmaxf(wm2, __shfl_xor_sync(FULLMASK, wm2, off));
    if (lane == 0) { warpmax[wid] = wm; warp2nd[wid] = wm2; }
    __syncthreads();

    if (tid == 0) {
        // t0 = 7th-smallest warp-2nd-max: 26 warps contribute >= 2 samples >= t0
        // -> >= 52 row elements >= t0 -> t0 <= row's 50th largest.
        float a[32];
        float M = warpmax[0];
        for (int w = 0; w < 32; w++) { a[w] = warp2nd[w]; M = fmaxf(M, warpmax[w]); }
        for (int k = 0; k < 7; k++) {
            int mi = k;
            for (int j = k + 1; j < 32; j++) if (a[j] < a[mi]) mi = j;
            float t = a[k]; a[k] = a[mi]; a[mi] = t;
        }
        g_t0[blockIdx.x] = a[6];
        g_M[blockIdx.x]  = M;
        g_cnt[blockIdx.x * 32] = 0;
    }
}

// ======================= K1: balanced streaming filter + candidate append =======================
__global__ __launch_bounds__(K1_NT, 4)
void k1_stream(const float* __restrict__ in, float* __restrict__ out) {
    const int row   = blockIdx.x >> 3;      // / CPR
    const int chunk = blockIdx.x & (CPR - 1);
    const int lane  = threadIdx.x & 31;
    const float t0  = g_t0[row];

    const float4* __restrict__ x4 = (const float4*)(in  + (size_t)row * VOCAB) + chunk * CF4;
    float4* __restrict__ y4       = (float4*)(out + (size_t)row * VOCAB) + chunk * CF4;
    const int gbase = chunk * CF4 * 4;      // element-index base within row
    int* __restrict__ cnt = &g_cnt[row * 32];
    unsigned long long* __restrict__ cand = &g_cand[(size_t)row * CAP];

#pragma unroll
    for (int it = 0; it < K1_IT; it++) {
        const int i = threadIdx.x + it * K1_NT;
        const bool ok = (i < CF4);
        float4 v = make_float4(NEGV, NEGV, NEGV, NEGV);
        if (ok) v = x4[i];
        if (ok) {
            float4 w;
            w.x = (v.x >= t0) ? v.x : NEGV;
            w.y = (v.y >= t0) ? v.y : NEGV;
            w.z = (v.z >= t0) ? v.z : NEGV;
            w.w = (v.w >= t0) ? v.w : NEGV;
            __stcs(&y4[i], w);
        }
        // warp-aggregated global append (all lanes participate; ok==false lanes contribute 0)
        unsigned m0 = __ballot_sync(FULLMASK, ok && v.x >= t0);
        unsigned m1 = __ballot_sync(FULLMASK, ok && v.y >= t0);
        unsigned m2 = __ballot_sync(FULLMASK, ok && v.z >= t0);
        unsigned m3 = __ballot_sync(FULLMASK, ok && v.w >= t0);
        int total = __popc(m0) + __popc(m1) + __popc(m2) + __popc(m3);
        if (total) {
            int base = 0;
            if (lane == 0) base = atomicAdd(cnt, total);
            base = __shfl_sync(FULLMASK, base, 0);
            const unsigned lt = (1u << lane) - 1u;
            int off = base;
            if (v.x >= t0 && ok) { int p = off + __popc(m0 & lt); if (p < CAP) cand[p] = ((unsigned long long)__float_as_uint(v.x) << 32) | (unsigned)(gbase + 4 * i); }
            off += __popc(m0);
            if (v.y >= t0 && ok) { int p = off + __popc(m1 & lt); if (p < CAP) cand[p] = ((unsigned long long)__float_as_uint(v.y) << 32) | (unsigned)(gbase + 4 * i + 1); }
            off += __popc(m1);
            if (v.z >= t0 && ok) { int p = off + __popc(m2 & lt); if (p < CAP) cand[p] = ((unsigned long long)__float_as_uint(v.z) << 32) | (unsigned)(gbase + 4 * i + 2); }
            off += __popc(m2);
            if (v.w >= t0 && ok) { int p = off + __popc(m3 & lt); if (p < CAP) cand[p] = ((unsigned long long)__float_as_uint(v.w) << 32) | (unsigned)(gbase + 4 * i + 3); }
        }
    }
}

// ======================= K2: per-row top-50 select + threshold + fixup =======================
__global__ __launch_bounds__(1024, 2)
void k2_select(float* __restrict__ out) {
    __shared__ int   hist[1024];
    __shared__ float topbuf[SUBCAP];
    __shared__ float topsorted[50];
    __shared__ float e50[50];
    __shared__ int   s_scnt, s_b1;
    __shared__ float s_thresh;

    const int tid  = threadIdx.x;
    const int lane = tid & 31;
    const int wid  = tid >> 5;
    const int row  = blockIdx.x;
    const unsigned long long* __restrict__ cand = &g_cand[(size_t)row * CAP];
    float* __restrict__ y = out + (size_t)row * VOCAB;

    int cnt = g_cnt[row * 32];
    if (cnt > CAP) cnt = CAP;
    const float t0 = g_t0[row];
    const float M  = g_M[row];
    const float scale = (M > t0) ? (1023.0f / (M - t0)) : 0.0f;

    hist[tid] = 0;
    if (tid == 0) { s_scnt = 0; s_b1 = 0; }
    if (tid < 50) topsorted[tid] = NEGV;
    __syncthreads();

    // histogram
    for (int i = tid; i < cnt; i += 1024) {
        float v = __uint_as_float((unsigned)(cand[i] >> 32));
        int b = (int)((v - t0) * scale);
        b = b < 0 ? 0 : (b > 1023 ? 1023 : b);
        atomicAdd(&hist[b], 1);
    }
    __syncthreads();

    // B1 = largest bin with suffix count >= 50 (warp 0)
    if (wid == 0) {
        int c = 0;
        for (int j = 0; j < 32; j++) c += hist[lane * 32 + j];
        int s = c;
#pragma unroll
        for (int off = 1; off < 32; off <<= 1) {
            int t = __shfl_down_sync(FULLMASK, s, off);
            if (lane + off < 32) s += t;
        }
        unsigned bb = __ballot_sync(FULLMASK, (s >= 50) && (s - c < 50));
        if (bb) {
            int L = __ffs(bb) - 1;
            if (lane == L) {
                int acc = s - c;
                int B1 = L * 32;
                for (int j = 31; j >= 0; j--) {
                    acc += hist[L * 32 + j];
                    if (acc >= 50) { B1 = L * 32 + j; break; }
                }
                s_b1 = B1;
            }
        }
    }
    __syncthreads();
    const int B1 = s_b1;

    // sub-candidates (bin >= B1)
    for (int i = tid; i < cnt; i += 1024) {
        float v = __uint_as_float((unsigned)(cand[i] >> 32));
        int b = (int)((v - t0) * scale);
        b = b < 0 ? 0 : (b > 1023 ? 1023 : b);
        if (b >= B1) { int p = atomicAdd(&s_scnt, 1); if (p < SUBCAP) topbuf[p] = v; }
    }
    __syncthreads();
    int sn = s_scnt; if (sn > SUBCAP) sn = SUBCAP;

    // rank-sort, keep top 50 descending
    for (int i = tid; i < sn; i += 1024) {
        float vi = topbuf[i];
        int r = 0;
        for (int j = 0; j < sn; j++) {
            float vj = topbuf[j];
            r += (vj > vi) || (vj == vi && j < i);
        }
        if (r < 50) topsorted[r] = vi;
    }
    __syncthreads();

    // softmax over top-50 + nucleus cutoff (reference's shifted-cumsum rule)
    if (tid < 50) e50[tid] = expf(topsorted[tid] - topsorted[0]);
    __syncthreads();
    if (tid == 0) {
        float S = 0.0f;
        for (int i = 0; i < 50; i++) S += e50[i];
        float inv = 1.0f / S;
        float cum = e50[0] * inv;
        int m = 1;
        for (int i = 1; i < 50; i++) {
            if (cum <= 0.9f) m++;
            cum += e50[i] * inv;
        }
        s_thresh = topsorted[m - 1];
    }
    __syncthreads();

    // scatter fixup
    const float t = s_thresh;
    for (int i = tid; i < cnt; i += 1024) {
        unsigned long long c = cand[i];
        float v = __uint_as_float((unsigned)(c >> 32));
        if (v < t) y[(unsigned)(c & 0xffffffffu)] = NEGV;
    }
}

extern "C" void kernel_launch(void* const* d_in, const int* in_sizes, int n_in,
                              void* d_out, int out_size) {
    const float* logits = (const float*)d_in[0];
    float* out = (float*)d_out;
    const int rows = out_size / VOCAB;  // 256
    k0_sample<<<rows, 1024>>>(logits);
    k1_stream<<<rows * CPR, K1_NT>>>(logits, out);
    k2_select<<<rows, 1024>>>(out);
}

// round 6
// speedup vs baseline: 1.2672x; 1.2672x over previous
#include <cuda_runtime.h>

#define VOCAB 128000
#define VOCAB4 (VOCAB / 4)
#define NT 1024
#define CAP 6144
#define SUBCAP 512
#define NEGV (-1000000000.0f)
#define FULLMASK 0xffffffffu

#define DYN_SMEM (CAP * 8 + 1024 * 4)   // buf + bidx + hist = 53248 bytes

__global__ __launch_bounds__(NT, 2)
void topk_topp_fused(const float* __restrict__ in, float* __restrict__ out) {
    extern __shared__ char dyn[];
    float* buf  = (float*)dyn;                  // CAP candidate values
    int*   bidx = (int*)(dyn + CAP * 4);        // CAP candidate indices
    int*   hist = (int*)(dyn + CAP * 8);        // 1024 bins

    __shared__ float warp2nd[32];
    __shared__ float warpmax[32];
    __shared__ float topbuf[SUBCAP];
    __shared__ float topsorted[50];
    __shared__ float e50[50];
    __shared__ int   s_cnt, s_scnt, s_b1;
    __shared__ float s_t0, s_M, s_thresh;

    const int tid  = threadIdx.x;
    const int lane = tid & 31;
    const int wid  = tid >> 5;
    const float* __restrict__ x = in  + (size_t)blockIdx.x * VOCAB;
    float* __restrict__ y       = out + (size_t)blockIdx.x * VOCAB;

    // ---------- Phase 0: init ----------
    hist[tid] = 0;
    if (tid == 0) { s_cnt = 0; s_scnt = 0; s_b1 = 0; }
    if (tid < 50) topsorted[tid] = NEGV;

    // ---------- Phase 1: sample 8192 elems, per-warp top-2 ----------
    const float4* __restrict__ xs = (const float4*)(x + wid * 4000);
    float4 sa = xs[lane * 2];
    float4 sb = xs[lane * 2 + 1];
    float sv[8] = {sa.x, sa.y, sa.z, sa.w, sb.x, sb.y, sb.z, sb.w};

    float lm = sv[0];
#pragma unroll
    for (int k = 1; k < 8; k++) lm = fmaxf(lm, sv[k]);
    float wm = lm;
#pragma unroll
    for (int off = 16; off > 0; off >>= 1)
        wm = fmaxf(wm, __shfl_xor_sync(FULLMASK, wm, off));
    unsigned bal = __ballot_sync(FULLMASK, lm == wm);
    if (lane == (__ffs(bal) - 1)) {
        bool done = false;
#pragma unroll
        for (int k = 0; k < 8; k++)
            if (!done && sv[k] == wm) { sv[k] = -3.4e38f; done = true; }
    }
    float lm2 = sv[0];
#pragma unroll
    for (int k = 1; k < 8; k++) lm2 = fmaxf(lm2, sv[k]);
    float wm2 = lm2;
#pragma unroll
    for (int off = 16; off > 0; off >>= 1)
        wm2 = fmaxf(wm2, __shfl_xor_sync(FULLMASK, wm2, off));
    if (lane == 0) { warpmax[wid] = wm; warp2nd[wid] = wm2; }
    __syncthreads();

    if (tid == 0) {
        // t0 = 7th-smallest warp-2nd-max: 26 warps contribute >= 2 samples >= t0
        // -> >= 52 row elements >= t0 -> t0 <= row's 50th largest
        // -> candidate set provably contains the top-50.
        float a[32];
        float M = warpmax[0];
        for (int w = 0; w < 32; w++) { a[w] = warp2nd[w]; M = fmaxf(M, warpmax[w]); }
        for (int k = 0; k < 7; k++) {
            int mi = k;
            for (int j = k + 1; j < 32; j++) if (a[j] < a[mi]) mi = j;
            float t = a[k]; a[k] = a[mi]; a[mi] = t;
        }
        s_t0 = a[6];
        s_M  = M;
    }
    __syncthreads();
    const float t0 = s_t0;
    const float M  = s_M;
    const float scale = (M > t0) ? (1023.0f / (M - t0)) : 0.0f;

    // ---------- Phase 2: fused streaming pass; vote-gated rare collection ----------
    const float4* __restrict__ x4 = (const float4*)x;
    float4* __restrict__ y4 = (float4*)y;

    for (int i = tid; i < VOCAB4; i += 2 * NT) {
        const int j = i + NT;
        const bool hb = (j < VOCAB4);          // warp-uniform predicate
        float4 va = x4[i];
        float4 vb;
        if (hb) vb = x4[j]; else { vb.x = NEGV; vb.y = NEGV; vb.z = NEGV; vb.w = NEGV; }

        // common path: filter + streaming store
        float4 wa, wb;
        wa.x = (va.x >= t0) ? va.x : NEGV;
        wa.y = (va.y >= t0) ? va.y : NEGV;
        wa.z = (va.z >= t0) ? va.z : NEGV;
        wa.w = (va.w >= t0) ? va.w : NEGV;
        __stcs(&y4[i], wa);
        if (hb) {
            wb.x = (vb.x >= t0) ? vb.x : NEGV;
            wb.y = (vb.y >= t0) ? vb.y : NEGV;
            wb.z = (vb.z >= t0) ? vb.z : NEGV;
            wb.w = (vb.w >= t0) ? vb.w : NEGV;
            __stcs(&y4[j], wb);
        }

        // one warp-wide test gates all collection work (~3% taken)
        const float mxa = fmaxf(fmaxf(va.x, va.y), fmaxf(va.z, va.w));
        const float mxb = fmaxf(fmaxf(vb.x, vb.y), fmaxf(vb.z, vb.w));
        if (__any_sync(FULLMASK, fmaxf(mxa, mxb) >= t0)) {
            unsigned m0 = __ballot_sync(FULLMASK, va.x >= t0);
            unsigned m1 = __ballot_sync(FULLMASK, va.y >= t0);
            unsigned m2 = __ballot_sync(FULLMASK, va.z >= t0);
            unsigned m3 = __ballot_sync(FULLMASK, va.w >= t0);
            unsigned n0 = __ballot_sync(FULLMASK, vb.x >= t0);
            unsigned n1 = __ballot_sync(FULLMASK, vb.y >= t0);
            unsigned n2 = __ballot_sync(FULLMASK, vb.z >= t0);
            unsigned n3 = __ballot_sync(FULLMASK, vb.w >= t0);
            int total = __popc(m0) + __popc(m1) + __popc(m2) + __popc(m3)
                      + __popc(n0) + __popc(n1) + __popc(n2) + __popc(n3);
            int base = 0;
            if (lane == 0) base = atomicAdd(&s_cnt, total);
            base = __shfl_sync(FULLMASK, base, 0);
            const unsigned lt = (1u << lane) - 1u;
            int off = base;
#define EMIT(val, msk, idx)                                                         \
            if ((val) >= t0) {                                                      \
                int p = off + __popc((msk) & lt);                                   \
                if (p < CAP) {                                                      \
                    buf[p] = (val); bidx[p] = (idx);                                \
                    int b = (int)(((val) - t0) * scale);                            \
                    b = b < 0 ? 0 : (b > 1023 ? 1023 : b);                          \
                    atomicAdd(&hist[b], 1);                                         \
                }                                                                   \
            }                                                                       \
            off += __popc(msk);
            EMIT(va.x, m0, 4 * i)
            EMIT(va.y, m1, 4 * i + 1)
            EMIT(va.z, m2, 4 * i + 2)
            EMIT(va.w, m3, 4 * i + 3)
            EMIT(vb.x, n0, 4 * j)
            EMIT(vb.y, n1, 4 * j + 1)
            EMIT(vb.z, n2, 4 * j + 2)
            EMIT(vb.w, n3, 4 * j + 3)
#undef EMIT
        }
    }
    __syncthreads();
    int cnt = s_cnt; if (cnt > CAP) cnt = CAP;

    // ---------- Phase 4: B1 = largest bin with suffix count >= 50 (warp 0) ----------
    if (wid == 0) {
        int c = 0;
        for (int jj = 0; jj < 32; jj++) c += hist[lane * 32 + jj];
        int s = c;
#pragma unroll
        for (int off = 1; off < 32; off <<= 1) {
            int t = __shfl_down_sync(FULLMASK, s, off);
            if (lane + off < 32) s += t;
        }
        unsigned bb = __ballot_sync(FULLMASK, (s >= 50) && (s - c < 50));
        if (bb) {
            int L = __ffs(bb) - 1;
            if (lane == L) {
                int acc = s - c;
                int B1 = L * 32;
                for (int jj = 31; jj >= 0; jj--) {
                    acc += hist[L * 32 + jj];
                    if (acc >= 50) { B1 = L * 32 + jj; break; }
                }
                s_b1 = B1;
            }
        }
    }
    __syncthreads();
    const int B1 = s_b1;

    // ---------- Phase 5: sub-candidates (bin >= B1) ----------
    for (int i = tid; i < cnt; i += NT) {
        float v = buf[i];
        int b = (int)((v - t0) * scale);
        b = b < 0 ? 0 : (b > 1023 ? 1023 : b);
        if (b >= B1) { int p = atomicAdd(&s_scnt, 1); if (p < SUBCAP) topbuf[p] = v; }
    }
    __syncthreads();
    int sn = s_scnt; if (sn > SUBCAP) sn = SUBCAP;

    // ---------- Phase 6: rank-sort, keep top 50 descending ----------
    for (int i = tid; i < sn; i += NT) {
        float vi = topbuf[i];
        int r = 0;
        for (int jj = 0; jj < sn; jj++) {
            float vj = topbuf[jj];
            r += (vj > vi) || (vj == vi && jj < i);
        }
        if (r < 50) topsorted[r] = vi;
    }
    __syncthreads();

    // ---------- Phase 7: softmax over top-50 (parallel exp) + nucleus cutoff ----------
    if (tid < 50) e50[tid] = expf(topsorted[tid] - topsorted[0]);
    __syncthreads();
    if (tid == 0) {
        float S = 0.0f;
        for (int i = 0; i < 50; i++) S += e50[i];
        float inv = 1.0f / S;
        float cum = e50[0] * inv;
        int m = 1;
        for (int i = 1; i < 50; i++) {
            if (cum <= 0.9f) m++;
            cum += e50[i] * inv;
        }
        s_thresh = topsorted[m - 1];
    }
    __syncthreads();

    // ---------- Phase 8: scatter fixup of failed candidates ----------
    const float t = s_thresh;
    for (int i = tid; i < cnt; i += NT)
        if (buf[i] < t) y[bidx[i]] = NEGV;
}

extern "C" void kernel_launch(void* const* d_in, const int* in_sizes, int n_in,
                              void* d_out, int out_size) {
    const float* logits = (const float*)d_in[0];
    float* out = (float*)d_out;
    const int rows = out_size / VOCAB;  // 256
    cudaFuncSetAttribute(topk_topp_fused,
                         cudaFuncAttributeMaxDynamicSharedMemorySize, DYN_SMEM);
    topk_topp_fused<<<rows, NT, DYN_SMEM>>>(logits, out);
}